// round 11
// baseline (speedup 1.0000x reference)
#include <cuda_runtime.h>
#include <math.h>

#define BATCH   16
#define HEADS   32
#define HDIM    128
#define NBLK    1024
#define BLKSZ   16
#define MAXB    128
#define HIDDEN  (HEADS * HDIM)
#define EPS     1e-6f
#define SCALE   0.08838834764831845f   // 1/sqrt(128)
#define NWARP   8
#define CHUNK   128                     // fixed tokens per split CTA
#define ZMAX    16                      // max splits: MAXB*BLKSZ / CHUNK

// allocation-free scratch (g_cnt zero-init; reset by merge warp each run)
__device__ float        g_pm[BATCH * HEADS * ZMAX];
__device__ float        g_pl[BATCH * HEADS * ZMAX];
__device__ float        g_pacc[BATCH * HEADS * ZMAX * HDIM];
__device__ unsigned int g_cnt[BATCH * HEADS];

// ---------------------------------------------------------------------------
// Kernel 1: split-KV paged flash-decode with FUSED RMSNorm prologue.
// (R8 mainloop, known-good codegen) + per-(b,h) completion counter.
// ---------------------------------------------------------------------------
__global__ __launch_bounds__(256, 4)
void attn_split_kernel(const float* __restrict__ kc,
                       const float* __restrict__ vc,
                       const int*   __restrict__ bt,
                       const int*   __restrict__ ctx,
                       const float* __restrict__ hidden,
                       const float* __restrict__ rmsw) {
    // let the PDL-attributed reduce grid launch while we stream
    cudaTriggerProgrammaticLaunchCompletion();

    const int h = blockIdx.x;
    const int b = blockIdx.y;
    const int z = blockIdx.z;
    const int tid  = threadIdx.x;
    const int lane = tid & 31;
    const int warp = tid >> 5;

    const int L     = ctx[b];
    const int start = z * CHUNK;
    if (start >= L) return;                       // inactive split: exit fast
    const int end   = min(start + CHUNK, L);
    const int bh    = b * HEADS + h;
    const int pidx  = bh * ZMAX + z;

    __shared__ float4 sq[HDIM / 4];
    __shared__ int    sbt[MAXB];
    __shared__ float  red[NWARP];
    __shared__ float  sm_m[NWARP], sm_l[NWARP];
    __shared__ float4 sm_acc[NWARP][HDIM / 4];

    // ---- fused RMSNorm prologue (hidden row is L2-hot) --------------------
    const float4* hrow = (const float4*)(hidden + b * HIDDEN);
    float ss = 0.f;
    #pragma unroll
    for (int i = 0; i < 4; i++) {
        float4 v = hrow[tid + i * 256];
        ss += v.x * v.x + v.y * v.y + v.z * v.z + v.w * v.w;
    }
    int btr = 0;
    if (tid < MAXB) btr = bt[b * MAXB + tid];

    #pragma unroll
    for (int o = 16; o; o >>= 1) ss += __shfl_xor_sync(~0u, ss, o);
    if (lane == 0) red[warp] = ss;
    if (tid < MAXB) sbt[tid] = btr;
    __syncthreads();
    if (tid < 32) {
        float s = (tid < NWARP) ? red[tid] : 0.f;
        #pragma unroll
        for (int o = 4; o; o >>= 1) s += __shfl_xor_sync(~0u, s, o);
        if (tid == 0) red[0] = s;
    }
    __syncthreads();
    const float inv = rsqrtf(red[0] * (1.0f / HIDDEN) + EPS);
    if (tid < HDIM / 4) {
        float4 v = ((const float4*)(hidden + b * HIDDEN + h * HDIM))[tid];
        float4 g = ((const float4*)rmsw)[h * (HDIM / 4) + tid];
        float4 o;
        o.x = v.x * inv * g.x;
        o.y = v.y * inv * g.y;
        o.z = v.z * inv * g.z;
        o.w = v.w * inv * g.w;
        sq[tid] = o;
    }
    __syncthreads();
    // -----------------------------------------------------------------------

    const float4 q4 = sq[lane];

    float  m = -INFINITY, l = 0.f;
    float4 acc = make_float4(0.f, 0.f, 0.f, 0.f);

    int s = start + warp;
    // 2 tokens/iter -> 4 independent LDG.128 in flight per warp
    for (; s + NWARP < end; s += 2 * NWARP) {
        const int sa = s, sb2 = s + NWARP;
        const size_t offa = (((size_t)sbt[sa  >> 4] * BLKSZ + (sa  & 15)) * HEADS + h) * HDIM;
        const size_t offb = (((size_t)sbt[sb2 >> 4] * BLKSZ + (sb2 & 15)) * HEADS + h) * HDIM;
        float4 ka = ((const float4*)(kc + offa))[lane];
        float4 kb = ((const float4*)(kc + offb))[lane];
        float4 va = ((const float4*)(vc + offa))[lane];
        float4 vb = ((const float4*)(vc + offb))[lane];

        float da = q4.x * ka.x + q4.y * ka.y + q4.z * ka.z + q4.w * ka.w;
        float db = q4.x * kb.x + q4.y * kb.y + q4.z * kb.z + q4.w * kb.w;
        #pragma unroll
        for (int o = 16; o; o >>= 1) {
            da += __shfl_xor_sync(~0u, da, o);
            db += __shfl_xor_sync(~0u, db, o);
        }
        const float s0 = da * SCALE;
        const float s1 = db * SCALE;

        const float m_new = fmaxf(m, fmaxf(s0, s1));
        const float corr  = __expf(m - m_new);
        const float p0    = __expf(s0 - m_new);
        const float p1    = __expf(s1 - m_new);
        l = l * corr + p0 + p1;
        acc.x = acc.x * corr + p0 * va.x + p1 * vb.x;
        acc.y = acc.y * corr + p0 * va.y + p1 * vb.y;
        acc.z = acc.z * corr + p0 * va.z + p1 * vb.z;
        acc.w = acc.w * corr + p0 * va.w + p1 * vb.w;
        m = m_new;
    }
    if (s < end) {
        const size_t off = (((size_t)sbt[s >> 4] * BLKSZ + (s & 15)) * HEADS + h) * HDIM;
        float4 k4 = ((const float4*)(kc + off))[lane];
        float4 v4 = ((const float4*)(vc + off))[lane];
        float d = q4.x * k4.x + q4.y * k4.y + q4.z * k4.z + q4.w * k4.w;
        #pragma unroll
        for (int o = 16; o; o >>= 1) d += __shfl_xor_sync(~0u, d, o);
        const float sc = d * SCALE;
        const float m_new = fmaxf(m, sc);
        const float corr  = __expf(m - m_new);
        const float p     = __expf(sc - m_new);
        l = l * corr + p;
        acc.x = acc.x * corr + p * v4.x;
        acc.y = acc.y * corr + p * v4.y;
        acc.z = acc.z * corr + p * v4.z;
        acc.w = acc.w * corr + p * v4.w;
        m = m_new;
    }

    // cross-warp merge (empty warps carry m=-inf and contribute c=0)
    if (lane == 0) { sm_m[warp] = m; sm_l[warp] = l; }
    sm_acc[warp][lane] = acc;
    __syncthreads();

    if (warp == 0) {
        float gm = -INFINITY;
        #pragma unroll
        for (int w = 0; w < NWARP; w++) gm = fmaxf(gm, sm_m[w]);
        float  gl = 0.f;
        float4 ga = make_float4(0.f, 0.f, 0.f, 0.f);
        #pragma unroll
        for (int w = 0; w < NWARP; w++) {
            const float c = __expf(sm_m[w] - gm);
            gl += sm_l[w] * c;
            float4 a = sm_acc[w][lane];
            ga.x += a.x * c; ga.y += a.y * c; ga.z += a.z * c; ga.w += a.w * c;
        }
        if (lane == 0) { g_pm[pidx] = gm; g_pl[pidx] = gl; }
        ((float4*)(g_pacc + (size_t)pidx * HDIM))[lane] = ga;
        // publish: release partials, signal readiness for this (b,h)
        __threadfence();
        if (lane == 0) atomicAdd(&g_cnt[bh], 1u);
    }
}

// ---------------------------------------------------------------------------
// Kernel 2: hook-style merge. One warp per (b,h); spins on that group's
// counter and merges AS SOON AS its splits are done — overlapped with the
// rest of the attn grid. PDL (PSS) launch + early trigger in attn lets these
// CTAs co-reside with attn (10K regs + 256 thr fit beside 4 attn CTAs/SM).
// ---------------------------------------------------------------------------
__global__ __launch_bounds__(256)
void attn_reduce_kernel(const float* __restrict__ hidden,
                        const int*   __restrict__ ctx,
                        float*       __restrict__ out) {
    const int warp = threadIdx.x >> 5;
    const int lane = threadIdx.x & 31;
    const int h = blockIdx.x * 8 + warp;
    const int b = blockIdx.y;
    const int bh   = b * HEADS + h;
    const int base = bh * ZMAX;

    // independent reads first
    const int   L  = ctx[b];
    const int   nz = (L + CHUNK - 1) / CHUNK;
    float4 r = ((const float4*)(hidden + b * HIDDEN + h * HDIM))[lane];

    // wait for this group's splits only (>= handles stale counts from
    // back-to-back attn replays under serialized profiling)
    if (lane == 0) {
        while (*((volatile unsigned int*)&g_cnt[bh]) < (unsigned int)nz)
            __nanosleep(256);
    }
    __syncwarp();
    __threadfence();                    // acquire partials

    // lane z: load partial stats in parallel (L2, bypass L1)
    float pm = (lane < nz) ? __ldcg(&g_pm[base + lane]) : -INFINITY;
    float pl = (lane < nz) ? __ldcg(&g_pl[base + lane]) : 0.f;
    float gm = pm;
    #pragma unroll
    for (int o = 16; o; o >>= 1) gm = fmaxf(gm, __shfl_xor_sync(~0u, gm, o));
    const float c_own = (lane < nz) ? __expf(pm - gm) : 0.f;
    float gl = pl * c_own;
    #pragma unroll
    for (int o = 16; o; o >>= 1) gl += __shfl_xor_sync(~0u, gl, o);

    // accumulate nz independent float4 streams
    float4 ga = make_float4(0.f, 0.f, 0.f, 0.f);
    #pragma unroll 4
    for (int zz = 0; zz < nz; zz++) {
        const float cz = __shfl_sync(~0u, c_own, zz);
        const float4* pa = (const float4*)(g_pacc + (size_t)(base + zz) * HDIM);
        float4 a = __ldcg(pa + lane);
        ga.x += cz * a.x; ga.y += cz * a.y;
        ga.z += cz * a.z; ga.w += cz * a.w;
    }

    const float invl = 1.0f / gl;
    float4 o;
    o.x = r.x + ga.x * invl;
    o.y = r.y + ga.y * invl;
    o.z = r.z + ga.z * invl;
    o.w = r.w + ga.w * invl;
    ((float4*)(out + b * HIDDEN + h * HDIM))[lane] = o;

    // reset counter for the next replay (only this warp owns bh)
    if (lane == 0) g_cnt[bh] = 0u;
}

// ---------------------------------------------------------------------------
extern "C" void kernel_launch(void* const* d_in, const int* in_sizes, int n_in,
                              void* d_out, int out_size) {
    const float* hidden = (const float*)d_in[0];
    const float* kcache = (const float*)d_in[1];
    const float* vcache = (const float*)d_in[2];
    const int*   btab   = (const int*)  d_in[3];
    const int*   clen   = (const int*)  d_in[4];
    const float* rmsw   = (const float*)d_in[5];
    float* out = (float*)d_out;

    attn_split_kernel<<<dim3(HEADS, BATCH, ZMAX), 256>>>(
        kcache, vcache, btab, clen, hidden, rmsw);

    // reduce: PDL secondary; attn's early trigger lets it launch + spin
    // while attn is still streaming KV
    {
        cudaLaunchConfig_t cfg = {};
        cfg.gridDim  = dim3(HEADS / 8, BATCH);
        cfg.blockDim = dim3(256);
        cudaLaunchAttribute at[1];
        at[0].id = cudaLaunchAttributeProgrammaticStreamSerialization;
        at[0].val.programmaticStreamSerializationAllowed = 1;
        cfg.attrs = at;
        cfg.numAttrs = 1;
        cfg.stream = 0;
        cudaLaunchKernelEx(&cfg, attn_reduce_kernel, hidden, clen, out);
    }
}

// round 12
// speedup vs baseline: 1.0395x; 1.0395x over previous
#include <cuda_runtime.h>
#include <math.h>

#define BATCH   16
#define HEADS   32
#define HDIM    128
#define NBLK    1024
#define BLKSZ   16
#define MAXB    128
#define HIDDEN  (HEADS * HDIM)
#define EPS     1e-6f
#define SCALE   0.08838834764831845f   // 1/sqrt(128)
#define NWARP   8
#define CHUNK   128                     // fixed tokens per split CTA
#define ZMAX    16                      // max splits: MAXB*BLKSZ / CHUNK

// allocation-free scratch
__device__ float g_pm[BATCH * HEADS * ZMAX];
__device__ float g_pl[BATCH * HEADS * ZMAX];
__device__ float g_pacc[BATCH * HEADS * ZMAX * HDIM];

// ---------------------------------------------------------------------------
// Kernel 1: split-KV paged flash-decode, 2 HEADS PER CTA, fused RMSNorm
// prologue. CTA = (head-pair, batch, z); tokens [z*128, min(z*128+128, L)).
// Per token the CTA reads a contiguous 1024B K row pair + 1024B V row pair.
// ---------------------------------------------------------------------------
__global__ __launch_bounds__(256, 4)
void attn_split_kernel(const float* __restrict__ kc,
                       const float* __restrict__ vc,
                       const int*   __restrict__ bt,
                       const int*   __restrict__ ctx,
                       const float* __restrict__ hidden,
                       const float* __restrict__ rmsw) {
    const int h0 = blockIdx.x * 2;               // first head of the pair
    const int b  = blockIdx.y;
    const int z  = blockIdx.z;
    const int tid  = threadIdx.x;
    const int lane = tid & 31;
    const int warp = tid >> 5;

    const int L     = ctx[b];
    const int start = z * CHUNK;
    if (start >= L) return;                       // inactive split
    const int end   = min(start + CHUNK, L);
    const int pidx0 = (b * HEADS + h0) * ZMAX + z;

    __shared__ float4 sq[2 * HDIM / 4];           // q for both heads (64 f4)
    __shared__ int    sbt[MAXB];
    __shared__ float  red[NWARP];
    __shared__ float  sm_m[NWARP][2], sm_l[NWARP][2];
    __shared__ float4 sm_acc[NWARP][2][HDIM / 4];

    // ---- fused RMSNorm prologue (hidden row is L2-hot) --------------------
    const float4* hrow = (const float4*)(hidden + b * HIDDEN);
    float ss = 0.f;
    #pragma unroll
    for (int i = 0; i < 4; i++) {
        float4 v = hrow[tid + i * 256];
        ss += v.x * v.x + v.y * v.y + v.z * v.z + v.w * v.w;
    }
    int btr = 0;
    if (tid < MAXB) btr = bt[b * MAXB + tid];

    #pragma unroll
    for (int o = 16; o; o >>= 1) ss += __shfl_xor_sync(~0u, ss, o);
    if (lane == 0) red[warp] = ss;
    if (tid < MAXB) sbt[tid] = btr;
    __syncthreads();
    if (tid < 32) {
        float s = (tid < NWARP) ? red[tid] : 0.f;
        #pragma unroll
        for (int o = 4; o; o >>= 1) s += __shfl_xor_sync(~0u, s, o);
        if (tid == 0) red[0] = s;
    }
    __syncthreads();
    const float inv = rsqrtf(red[0] * (1.0f / HIDDEN) + EPS);
    if (tid < 2 * HDIM / 4) {                     // 64 f4 = both heads' q
        float4 v = ((const float4*)(hidden + b * HIDDEN + h0 * HDIM))[tid];
        float4 g = ((const float4*)rmsw)[h0 * (HDIM / 4) + tid];
        float4 o;
        o.x = v.x * inv * g.x;
        o.y = v.y * inv * g.y;
        o.z = v.z * inv * g.z;
        o.w = v.w * inv * g.w;
        sq[tid] = o;
    }
    __syncthreads();
    // -----------------------------------------------------------------------

    const float4 qa = sq[lane];                   // head A
    const float4 qb = sq[32 + lane];              // head B

    float  ma = -INFINITY, la = 0.f;
    float  mb = -INFINITY, lb = 0.f;
    float4 accA = make_float4(0.f, 0.f, 0.f, 0.f);
    float4 accB = make_float4(0.f, 0.f, 0.f, 0.f);

    // 1 token/iter, 2 heads -> 4 independent LDG.128 in flight per warp
    for (int s = start + warp; s < end; s += NWARP) {
        const size_t off = (((size_t)sbt[s >> 4] * BLKSZ + (s & 15)) * HEADS + h0) * HDIM;
        float4 ka = ((const float4*)(kc + off))[lane];
        float4 kb = ((const float4*)(kc + off + HDIM))[lane];
        float4 va = ((const float4*)(vc + off))[lane];
        float4 vb = ((const float4*)(vc + off + HDIM))[lane];

        float da = qa.x * ka.x + qa.y * ka.y + qa.z * ka.z + qa.w * ka.w;
        float db = qb.x * kb.x + qb.y * kb.y + qb.z * kb.z + qb.w * kb.w;
        #pragma unroll
        for (int o = 16; o; o >>= 1) {
            da += __shfl_xor_sync(~0u, da, o);
            db += __shfl_xor_sync(~0u, db, o);
        }
        const float s0 = da * SCALE;
        const float s1 = db * SCALE;

        const float ma_n = fmaxf(ma, s0);
        const float ca   = __expf(ma - ma_n);
        const float pa   = __expf(s0 - ma_n);
        la = la * ca + pa;
        accA.x = accA.x * ca + pa * va.x;
        accA.y = accA.y * ca + pa * va.y;
        accA.z = accA.z * ca + pa * va.z;
        accA.w = accA.w * ca + pa * va.w;
        ma = ma_n;

        const float mb_n = fmaxf(mb, s1);
        const float cb   = __expf(mb - mb_n);
        const float pb   = __expf(s1 - mb_n);
        lb = lb * cb + pb;
        accB.x = accB.x * cb + pb * vb.x;
        accB.y = accB.y * cb + pb * vb.y;
        accB.z = accB.z * cb + pb * vb.z;
        accB.w = accB.w * cb + pb * vb.w;
        mb = mb_n;
    }

    // cross-warp merge (empty warps carry m=-inf and contribute c=0)
    if (lane == 0) {
        sm_m[warp][0] = ma; sm_l[warp][0] = la;
        sm_m[warp][1] = mb; sm_l[warp][1] = lb;
    }
    sm_acc[warp][0][lane] = accA;
    sm_acc[warp][1][lane] = accB;
    __syncthreads();

    if (warp < 2) {                               // warp 0: head A, warp 1: head B
        const int hh = warp;
        float gm = -INFINITY;
        #pragma unroll
        for (int w = 0; w < NWARP; w++) gm = fmaxf(gm, sm_m[w][hh]);
        float  gl = 0.f;
        float4 ga = make_float4(0.f, 0.f, 0.f, 0.f);
        #pragma unroll
        for (int w = 0; w < NWARP; w++) {
            const float c = __expf(sm_m[w][hh] - gm);
            gl += sm_l[w][hh] * c;
            float4 a = sm_acc[w][hh][lane];
            ga.x += a.x * c; ga.y += a.y * c; ga.z += a.z * c; ga.w += a.w * c;
        }
        const int pidx = pidx0 + hh * ZMAX;       // (b*HEADS + h0+hh)*ZMAX + z
        if (lane == 0) { g_pm[pidx] = gm; g_pl[pidx] = gl; }
        ((float4*)(g_pacc + (size_t)pidx * HDIM))[lane] = ga;
    }
}

// ---------------------------------------------------------------------------
// Kernel 2: warp-parallel merge (R8, unchanged). One warp per (b,h). PDL.
// ---------------------------------------------------------------------------
__global__ __launch_bounds__(256)
void attn_reduce_kernel(const float* __restrict__ hidden,
                        const int*   __restrict__ ctx,
                        float*       __restrict__ out) {
    const int warp = threadIdx.x >> 5;
    const int lane = threadIdx.x & 31;
    const int h = blockIdx.x * 8 + warp;
    const int b = blockIdx.y;
    const int base = (b * HEADS + h) * ZMAX;

    // independent reads first (overlap attn tail under PDL)
    const int   L  = ctx[b];
    const int   nz = (L + CHUNK - 1) / CHUNK;
    float4 r = ((const float4*)(hidden + b * HIDDEN + h * HDIM))[lane];

    cudaGridDependencySynchronize();    // wait for attn partials

    // lane z: load partial stats in parallel
    float pm = (lane < nz) ? g_pm[base + lane] : -INFINITY;
    float pl = (lane < nz) ? g_pl[base + lane] : 0.f;
    float gm = pm;
    #pragma unroll
    for (int o = 16; o; o >>= 1) gm = fmaxf(gm, __shfl_xor_sync(~0u, gm, o));
    const float c_own = (lane < nz) ? __expf(pm - gm) : 0.f;
    float gl = pl * c_own;
    #pragma unroll
    for (int o = 16; o; o >>= 1) gl += __shfl_xor_sync(~0u, gl, o);

    // accumulate nz independent float4 streams
    float4 ga = make_float4(0.f, 0.f, 0.f, 0.f);
    #pragma unroll 4
    for (int zz = 0; zz < nz; zz++) {
        const float cz = __shfl_sync(~0u, c_own, zz);
        float4 a = ((const float4*)(g_pacc + (size_t)(base + zz) * HDIM))[lane];
        ga.x += cz * a.x; ga.y += cz * a.y;
        ga.z += cz * a.z; ga.w += cz * a.w;
    }

    const float invl = 1.0f / gl;
    float4 o;
    o.x = r.x + ga.x * invl;
    o.y = r.y + ga.y * invl;
    o.z = r.z + ga.z * invl;
    o.w = r.w + ga.w * invl;
    ((float4*)(out + b * HIDDEN + h * HDIM))[lane] = o;
}

// ---------------------------------------------------------------------------
extern "C" void kernel_launch(void* const* d_in, const int* in_sizes, int n_in,
                              void* d_out, int out_size) {
    const float* hidden = (const float*)d_in[0];
    const float* kcache = (const float*)d_in[1];
    const float* vcache = (const float*)d_in[2];
    const int*   btab   = (const int*)  d_in[3];
    const int*   clen   = (const int*)  d_in[4];
    const float* rmsw   = (const float*)d_in[5];
    float* out = (float*)d_out;

    attn_split_kernel<<<dim3(HEADS / 2, BATCH, ZMAX), 256>>>(
        kcache, vcache, btab, clen, hidden, rmsw);

    // reduce: PDL so residual/ctx loads overlap attn's tail
    {
        cudaLaunchConfig_t cfg = {};
        cfg.gridDim  = dim3(HEADS / 8, BATCH);
        cfg.blockDim = dim3(256);
        cudaLaunchAttribute at[1];
        at[0].id = cudaLaunchAttributeProgrammaticStreamSerialization;
        at[0].val.programmaticStreamSerializationAllowed = 1;
        cfg.attrs = at;
        cfg.numAttrs = 1;
        cfg.stream = 0;
        cudaLaunchKernelEx(&cfg, attn_reduce_kernel, hidden, clen, out);
    }
}

// round 13
// speedup vs baseline: 1.0762x; 1.0353x over previous
#include <cuda_runtime.h>
#include <math.h>

#define BATCH   16
#define HEADS   32
#define HDIM    128
#define NBLK    1024
#define BLKSZ   16
#define MAXB    128
#define HIDDEN  (HEADS * HDIM)
#define EPS     1e-6f
#define SCALE   0.08838834764831845f   // 1/sqrt(128)
#define NWARP   8
#define CHUNK   128                     // fixed tokens per split CTA
#define ZMAX    16                      // max splits: MAXB*BLKSZ / CHUNK

// allocation-free scratch
__device__ float g_pm[BATCH * HEADS * ZMAX];
__device__ float g_pl[BATCH * HEADS * ZMAX];
__device__ float g_pacc[BATCH * HEADS * ZMAX * HDIM];

// ---------------------------------------------------------------------------
// Kernel 1: split-KV paged flash-decode with FUSED RMSNorm prologue.
// R8 mainloop (known-good codegen); grid reordered Z-FASTEST so active and
// inactive splits interleave uniformly across the launch sequence (no sparse
// tail of long-context high-z chunks).
// CTA = (z, head, batch); tokens [z*128, min(z*128+128, L)).
// ---------------------------------------------------------------------------
__global__ __launch_bounds__(256, 4)
void attn_split_kernel(const float* __restrict__ kc,
                       const float* __restrict__ vc,
                       const int*   __restrict__ bt,
                       const int*   __restrict__ ctx,
                       const float* __restrict__ hidden,
                       const float* __restrict__ rmsw) {
    const int z = blockIdx.x;                     // fastest-varying
    const int h = blockIdx.y;
    const int b = blockIdx.z;
    const int tid  = threadIdx.x;
    const int lane = tid & 31;
    const int warp = tid >> 5;

    const int L     = ctx[b];
    const int start = z * CHUNK;
    if (start >= L) return;                       // inactive split: exit fast
    const int end   = min(start + CHUNK, L);
    const int pidx  = (b * HEADS + h) * ZMAX + z;

    __shared__ float4 sq[HDIM / 4];
    __shared__ int    sbt[MAXB];
    __shared__ float  red[NWARP];
    __shared__ float  sm_m[NWARP], sm_l[NWARP];
    __shared__ float4 sm_acc[NWARP][HDIM / 4];

    // ---- fused RMSNorm prologue (hidden row is L2-hot) --------------------
    const float4* hrow = (const float4*)(hidden + b * HIDDEN);
    float ss = 0.f;
    #pragma unroll
    for (int i = 0; i < 4; i++) {
        float4 v = hrow[tid + i * 256];
        ss += v.x * v.x + v.y * v.y + v.z * v.z + v.w * v.w;
    }
    int btr = 0;
    if (tid < MAXB) btr = bt[b * MAXB + tid];

    #pragma unroll
    for (int o = 16; o; o >>= 1) ss += __shfl_xor_sync(~0u, ss, o);
    if (lane == 0) red[warp] = ss;
    if (tid < MAXB) sbt[tid] = btr;
    __syncthreads();
    if (tid < 32) {
        float s = (tid < NWARP) ? red[tid] : 0.f;
        #pragma unroll
        for (int o = 4; o; o >>= 1) s += __shfl_xor_sync(~0u, s, o);
        if (tid == 0) red[0] = s;
    }
    __syncthreads();
    const float inv = rsqrtf(red[0] * (1.0f / HIDDEN) + EPS);
    if (tid < HDIM / 4) {
        float4 v = ((const float4*)(hidden + b * HIDDEN + h * HDIM))[tid];
        float4 g = ((const float4*)rmsw)[h * (HDIM / 4) + tid];
        float4 o;
        o.x = v.x * inv * g.x;
        o.y = v.y * inv * g.y;
        o.z = v.z * inv * g.z;
        o.w = v.w * inv * g.w;
        sq[tid] = o;
    }
    __syncthreads();
    // -----------------------------------------------------------------------

    const float4 q4 = sq[lane];

    float  m = -INFINITY, l = 0.f;
    float4 acc = make_float4(0.f, 0.f, 0.f, 0.f);

    int s = start + warp;
    // 2 tokens/iter -> 4 independent LDG.128 in flight per warp
    for (; s + NWARP < end; s += 2 * NWARP) {
        const int sa = s, sb2 = s + NWARP;
        const size_t offa = (((size_t)sbt[sa  >> 4] * BLKSZ + (sa  & 15)) * HEADS + h) * HDIM;
        const size_t offb = (((size_t)sbt[sb2 >> 4] * BLKSZ + (sb2 & 15)) * HEADS + h) * HDIM;
        float4 ka = ((const float4*)(kc + offa))[lane];
        float4 kb = ((const float4*)(kc + offb))[lane];
        float4 va = ((const float4*)(vc + offa))[lane];
        float4 vb = ((const float4*)(vc + offb))[lane];

        float da = q4.x * ka.x + q4.y * ka.y + q4.z * ka.z + q4.w * ka.w;
        float db = q4.x * kb.x + q4.y * kb.y + q4.z * kb.z + q4.w * kb.w;
        #pragma unroll
        for (int o = 16; o; o >>= 1) {
            da += __shfl_xor_sync(~0u, da, o);
            db += __shfl_xor_sync(~0u, db, o);
        }
        const float s0 = da * SCALE;
        const float s1 = db * SCALE;

        const float m_new = fmaxf(m, fmaxf(s0, s1));
        const float corr  = __expf(m - m_new);
        const float p0    = __expf(s0 - m_new);
        const float p1    = __expf(s1 - m_new);
        l = l * corr + p0 + p1;
        acc.x = acc.x * corr + p0 * va.x + p1 * vb.x;
        acc.y = acc.y * corr + p0 * va.y + p1 * vb.y;
        acc.z = acc.z * corr + p0 * va.z + p1 * vb.z;
        acc.w = acc.w * corr + p0 * va.w + p1 * vb.w;
        m = m_new;
    }
    if (s < end) {
        const size_t off = (((size_t)sbt[s >> 4] * BLKSZ + (s & 15)) * HEADS + h) * HDIM;
        float4 k4 = ((const float4*)(kc + off))[lane];
        float4 v4 = ((const float4*)(vc + off))[lane];
        float d = q4.x * k4.x + q4.y * k4.y + q4.z * k4.z + q4.w * k4.w;
        #pragma unroll
        for (int o = 16; o; o >>= 1) d += __shfl_xor_sync(~0u, d, o);
        const float sc = d * SCALE;
        const float m_new = fmaxf(m, sc);
        const float corr  = __expf(m - m_new);
        const float p     = __expf(sc - m_new);
        l = l * corr + p;
        acc.x = acc.x * corr + p * v4.x;
        acc.y = acc.y * corr + p * v4.y;
        acc.z = acc.z * corr + p * v4.z;
        acc.w = acc.w * corr + p * v4.w;
        m = m_new;
    }

    // cross-warp merge (empty warps carry m=-inf and contribute c=0)
    if (lane == 0) { sm_m[warp] = m; sm_l[warp] = l; }
    sm_acc[warp][lane] = acc;
    __syncthreads();

    if (warp == 0) {
        float gm = -INFINITY;
        #pragma unroll
        for (int w = 0; w < NWARP; w++) gm = fmaxf(gm, sm_m[w]);
        float  gl = 0.f;
        float4 ga = make_float4(0.f, 0.f, 0.f, 0.f);
        #pragma unroll
        for (int w = 0; w < NWARP; w++) {
            const float c = __expf(sm_m[w] - gm);
            gl += sm_l[w] * c;
            float4 a = sm_acc[w][lane];
            ga.x += a.x * c; ga.y += a.y * c; ga.z += a.z * c; ga.w += a.w * c;
        }
        if (lane == 0) { g_pm[pidx] = gm; g_pl[pidx] = gl; }
        ((float4*)(g_pacc + (size_t)pidx * HDIM))[lane] = ga;
    }
}

// ---------------------------------------------------------------------------
// Kernel 2: warp-parallel merge (R8, unchanged). One warp per (b,h). PDL.
// ---------------------------------------------------------------------------
__global__ __launch_bounds__(256)
void attn_reduce_kernel(const float* __restrict__ hidden,
                        const int*   __restrict__ ctx,
                        float*       __restrict__ out) {
    const int warp = threadIdx.x >> 5;
    const int lane = threadIdx.x & 31;
    const int h = blockIdx.x * 8 + warp;
    const int b = blockIdx.y;
    const int base = (b * HEADS + h) * ZMAX;

    // independent reads first (overlap attn tail under PDL)
    const int   L  = ctx[b];
    const int   nz = (L + CHUNK - 1) / CHUNK;
    float4 r = ((const float4*)(hidden + b * HIDDEN + h * HDIM))[lane];

    cudaGridDependencySynchronize();    // wait for attn partials

    // lane z: load partial stats in parallel
    float pm = (lane < nz) ? g_pm[base + lane] : -INFINITY;
    float pl = (lane < nz) ? g_pl[base + lane] : 0.f;
    float gm = pm;
    #pragma unroll
    for (int o = 16; o; o >>= 1) gm = fmaxf(gm, __shfl_xor_sync(~0u, gm, o));
    const float c_own = (lane < nz) ? __expf(pm - gm) : 0.f;
    float gl = pl * c_own;
    #pragma unroll
    for (int o = 16; o; o >>= 1) gl += __shfl_xor_sync(~0u, gl, o);

    // accumulate nz independent float4 streams
    float4 ga = make_float4(0.f, 0.f, 0.f, 0.f);
    #pragma unroll 4
    for (int zz = 0; zz < nz; zz++) {
        const float cz = __shfl_sync(~0u, c_own, zz);
        float4 a = ((const float4*)(g_pacc + (size_t)(base + zz) * HDIM))[lane];
        ga.x += cz * a.x; ga.y += cz * a.y;
        ga.z += cz * a.z; ga.w += cz * a.w;
    }

    const float invl = 1.0f / gl;
    float4 o;
    o.x = r.x + ga.x * invl;
    o.y = r.y + ga.y * invl;
    o.z = r.z + ga.z * invl;
    o.w = r.w + ga.w * invl;
    ((float4*)(out + b * HIDDEN + h * HDIM))[lane] = o;
}

// ---------------------------------------------------------------------------
extern "C" void kernel_launch(void* const* d_in, const int* in_sizes, int n_in,
                              void* d_out, int out_size) {
    const float* hidden = (const float*)d_in[0];
    const float* kcache = (const float*)d_in[1];
    const float* vcache = (const float*)d_in[2];
    const int*   btab   = (const int*)  d_in[3];
    const int*   clen   = (const int*)  d_in[4];
    const float* rmsw   = (const float*)d_in[5];
    float* out = (float*)d_out;

    // z fastest-varying: active/inactive splits interleave uniformly
    attn_split_kernel<<<dim3(ZMAX, HEADS, BATCH), 256>>>(
        kcache, vcache, btab, clen, hidden, rmsw);

    // reduce: PDL so residual/ctx loads overlap attn's tail
    {
        cudaLaunchConfig_t cfg = {};
        cfg.gridDim  = dim3(HEADS / 8, BATCH);
        cfg.blockDim = dim3(256);
        cudaLaunchAttribute at[1];
        at[0].id = cudaLaunchAttributeProgrammaticStreamSerialization;
        at[0].val.programmaticStreamSerializationAllowed = 1;
        cfg.attrs = at;
        cfg.numAttrs = 1;
        cfg.stream = 0;
        cudaLaunchKernelEx(&cfg, attn_reduce_kernel, hidden, clen, out);
    }
}

// round 14
// speedup vs baseline: 1.1138x; 1.0349x over previous
#include <cuda_runtime.h>
#include <math.h>

#define BATCH   16
#define HEADS   32
#define HDIM    128
#define NBLK    1024
#define BLKSZ   16
#define MAXB    128
#define HIDDEN  (HEADS * HDIM)
#define EPS     1e-6f
#define SCALE   0.08838834764831845f   // 1/sqrt(128)
#define NWARP   8
#define CHUNK   128                     // fixed tokens per split CTA
#define ZMAX    16                      // max splits: MAXB*BLKSZ / CHUNK

// allocation-free scratch
__device__ float g_pm[BATCH * HEADS * ZMAX];
__device__ float g_pl[BATCH * HEADS * ZMAX];
__device__ float g_pacc[BATCH * HEADS * ZMAX * HDIM];

// ---------------------------------------------------------------------------
// Kernel 1: split-KV paged flash-decode with FUSED RMSNorm prologue.
// (R8 kernel, byte-identical — best measured configuration)
// ---------------------------------------------------------------------------
__global__ __launch_bounds__(256, 4)
void attn_split_kernel(const float* __restrict__ kc,
                       const float* __restrict__ vc,
                       const int*   __restrict__ bt,
                       const int*   __restrict__ ctx,
                       const float* __restrict__ hidden,
                       const float* __restrict__ rmsw) {
    const int h = blockIdx.x;
    const int b = blockIdx.y;
    const int z = blockIdx.z;
    const int tid  = threadIdx.x;
    const int lane = tid & 31;
    const int warp = tid >> 5;

    const int L     = ctx[b];
    const int start = z * CHUNK;
    if (start >= L) return;                       // inactive split: exit fast
    const int end   = min(start + CHUNK, L);
    const int pidx  = (b * HEADS + h) * ZMAX + z;

    __shared__ float4 sq[HDIM / 4];
    __shared__ int    sbt[MAXB];
    __shared__ float  red[NWARP];
    __shared__ float  sm_m[NWARP], sm_l[NWARP];
    __shared__ float4 sm_acc[NWARP][HDIM / 4];

    // ---- fused RMSNorm prologue (hidden row is L2-hot) --------------------
    const float4* hrow = (const float4*)(hidden + b * HIDDEN);
    float ss = 0.f;
    #pragma unroll
    for (int i = 0; i < 4; i++) {
        float4 v = hrow[tid + i * 256];
        ss += v.x * v.x + v.y * v.y + v.z * v.z + v.w * v.w;
    }
    int btr = 0;
    if (tid < MAXB) btr = bt[b * MAXB + tid];

    #pragma unroll
    for (int o = 16; o; o >>= 1) ss += __shfl_xor_sync(~0u, ss, o);
    if (lane == 0) red[warp] = ss;
    if (tid < MAXB) sbt[tid] = btr;
    __syncthreads();
    if (tid < 32) {
        float s = (tid < NWARP) ? red[tid] : 0.f;
        #pragma unroll
        for (int o = 4; o; o >>= 1) s += __shfl_xor_sync(~0u, s, o);
        if (tid == 0) red[0] = s;
    }
    __syncthreads();
    const float inv = rsqrtf(red[0] * (1.0f / HIDDEN) + EPS);
    if (tid < HDIM / 4) {
        float4 v = ((const float4*)(hidden + b * HIDDEN + h * HDIM))[tid];
        float4 g = ((const float4*)rmsw)[h * (HDIM / 4) + tid];
        float4 o;
        o.x = v.x * inv * g.x;
        o.y = v.y * inv * g.y;
        o.z = v.z * inv * g.z;
        o.w = v.w * inv * g.w;
        sq[tid] = o;
    }
    __syncthreads();
    // -----------------------------------------------------------------------

    const float4 q4 = sq[lane];

    float  m = -INFINITY, l = 0.f;
    float4 acc = make_float4(0.f, 0.f, 0.f, 0.f);

    int s = start + warp;
    // 2 tokens/iter -> 4 independent LDG.128 in flight per warp
    for (; s + NWARP < end; s += 2 * NWARP) {
        const int sa = s, sb2 = s + NWARP;
        const size_t offa = (((size_t)sbt[sa  >> 4] * BLKSZ + (sa  & 15)) * HEADS + h) * HDIM;
        const size_t offb = (((size_t)sbt[sb2 >> 4] * BLKSZ + (sb2 & 15)) * HEADS + h) * HDIM;
        float4 ka = ((const float4*)(kc + offa))[lane];
        float4 kb = ((const float4*)(kc + offb))[lane];
        float4 va = ((const float4*)(vc + offa))[lane];
        float4 vb = ((const float4*)(vc + offb))[lane];

        float da = q4.x * ka.x + q4.y * ka.y + q4.z * ka.z + q4.w * ka.w;
        float db = q4.x * kb.x + q4.y * kb.y + q4.z * kb.z + q4.w * kb.w;
        #pragma unroll
        for (int o = 16; o; o >>= 1) {
            da += __shfl_xor_sync(~0u, da, o);
            db += __shfl_xor_sync(~0u, db, o);
        }
        const float s0 = da * SCALE;
        const float s1 = db * SCALE;

        const float m_new = fmaxf(m, fmaxf(s0, s1));
        const float corr  = __expf(m - m_new);
        const float p0    = __expf(s0 - m_new);
        const float p1    = __expf(s1 - m_new);
        l = l * corr + p0 + p1;
        acc.x = acc.x * corr + p0 * va.x + p1 * vb.x;
        acc.y = acc.y * corr + p0 * va.y + p1 * vb.y;
        acc.z = acc.z * corr + p0 * va.z + p1 * vb.z;
        acc.w = acc.w * corr + p0 * va.w + p1 * vb.w;
        m = m_new;
    }
    if (s < end) {
        const size_t off = (((size_t)sbt[s >> 4] * BLKSZ + (s & 15)) * HEADS + h) * HDIM;
        float4 k4 = ((const float4*)(kc + off))[lane];
        float4 v4 = ((const float4*)(vc + off))[lane];
        float d = q4.x * k4.x + q4.y * k4.y + q4.z * k4.z + q4.w * k4.w;
        #pragma unroll
        for (int o = 16; o; o >>= 1) d += __shfl_xor_sync(~0u, d, o);
        const float sc = d * SCALE;
        const float m_new = fmaxf(m, sc);
        const float corr  = __expf(m - m_new);
        const float p     = __expf(sc - m_new);
        l = l * corr + p;
        acc.x = acc.x * corr + p * v4.x;
        acc.y = acc.y * corr + p * v4.y;
        acc.z = acc.z * corr + p * v4.z;
        acc.w = acc.w * corr + p * v4.w;
        m = m_new;
    }

    // cross-warp merge (empty warps carry m=-inf and contribute c=0)
    if (lane == 0) { sm_m[warp] = m; sm_l[warp] = l; }
    sm_acc[warp][lane] = acc;
    __syncthreads();

    if (warp == 0) {
        float gm = -INFINITY;
        #pragma unroll
        for (int w = 0; w < NWARP; w++) gm = fmaxf(gm, sm_m[w]);
        float  gl = 0.f;
        float4 ga = make_float4(0.f, 0.f, 0.f, 0.f);
        #pragma unroll
        for (int w = 0; w < NWARP; w++) {
            const float c = __expf(sm_m[w] - gm);
            gl += sm_l[w] * c;
            float4 a = sm_acc[w][lane];
            ga.x += a.x * c; ga.y += a.y * c; ga.z += a.z * c; ga.w += a.w * c;
        }
        if (lane == 0) { g_pm[pidx] = gm; g_pl[pidx] = gl; }
        ((float4*)(g_pacc + (size_t)pidx * HDIM))[lane] = ga;
    }
}

// ---------------------------------------------------------------------------
// Kernel 2: PARALLEL merge. One 128-thread CTA per (b,h) -> 512 CTAs spread
// over all SMs. Warp 0 computes softmax weights; all 4 warps concurrently
// load 4 independent z-slices each; two smem barriers combine. PDL.
// ---------------------------------------------------------------------------
__global__ __launch_bounds__(128)
void attn_reduce_kernel(const float* __restrict__ hidden,
                        const int*   __restrict__ ctx,
                        float*       __restrict__ out) {
    const int h = blockIdx.x;
    const int b = blockIdx.y;
    const int warp = threadIdx.x >> 5;
    const int lane = threadIdx.x & 31;
    const int base = (b * HEADS + h) * ZMAX;

    __shared__ float  sc[ZMAX];         // softmax weight per z
    __shared__ float  s_gl;
    __shared__ float4 part[4][HDIM / 4];

    // independent reads first (overlap attn tail under PDL)
    const int L  = ctx[b];
    const int nz = (L + CHUNK - 1) / CHUNK;
    float4 r = make_float4(0.f, 0.f, 0.f, 0.f);
    if (warp == 0) r = ((const float4*)(hidden + b * HIDDEN + h * HDIM))[lane];

    cudaGridDependencySynchronize();    // wait for attn partials

    // every warp issues its 4 independent z-slice loads immediately
    // (z = warp + 4*i stripes active z evenly across warps)
    float4 a[4];
    int    zi[4];
    #pragma unroll
    for (int i = 0; i < 4; i++) {
        const int zz = warp + 4 * i;
        zi[i] = zz;
        if (zz < nz)
            a[i] = ((const float4*)(g_pacc + (size_t)(base + zz) * HDIM))[lane];
        else
            a[i] = make_float4(0.f, 0.f, 0.f, 0.f);
    }

    // warp 0 (concurrently): stats -> weights
    if (warp == 0) {
        float pm = (lane < nz) ? g_pm[base + lane] : -INFINITY;
        float pl = (lane < nz) ? g_pl[base + lane] : 0.f;
        float gm = pm;
        #pragma unroll
        for (int o = 16; o; o >>= 1) gm = fmaxf(gm, __shfl_xor_sync(~0u, gm, o));
        const float c = (lane < nz) ? __expf(pm - gm) : 0.f;
        float gl = pl * c;
        #pragma unroll
        for (int o = 16; o; o >>= 1) gl += __shfl_xor_sync(~0u, gl, o);
        if (lane < ZMAX) sc[lane] = c;
        if (lane == 0)   s_gl = gl;
    }
    __syncthreads();

    // scale own slices by weights, partial-sum per warp
    float4 p = make_float4(0.f, 0.f, 0.f, 0.f);
    #pragma unroll
    for (int i = 0; i < 4; i++) {
        const float cz = (zi[i] < ZMAX) ? sc[zi[i]] : 0.f;
        p.x += cz * a[i].x; p.y += cz * a[i].y;
        p.z += cz * a[i].z; p.w += cz * a[i].w;
    }
    part[warp][lane] = p;
    __syncthreads();

    if (warp == 0) {
        float4 ga = part[0][lane];
        #pragma unroll
        for (int w = 1; w < 4; w++) {
            float4 q = part[w][lane];
            ga.x += q.x; ga.y += q.y; ga.z += q.z; ga.w += q.w;
        }
        const float invl = 1.0f / s_gl;
        float4 o;
        o.x = r.x + ga.x * invl;
        o.y = r.y + ga.y * invl;
        o.z = r.z + ga.z * invl;
        o.w = r.w + ga.w * invl;
        ((float4*)(out + b * HIDDEN + h * HDIM))[lane] = o;
    }
}

// ---------------------------------------------------------------------------
extern "C" void kernel_launch(void* const* d_in, const int* in_sizes, int n_in,
                              void* d_out, int out_size) {
    const float* hidden = (const float*)d_in[0];
    const float* kcache = (const float*)d_in[1];
    const float* vcache = (const float*)d_in[2];
    const int*   btab   = (const int*)  d_in[3];
    const int*   clen   = (const int*)  d_in[4];
    const float* rmsw   = (const float*)d_in[5];
    float* out = (float*)d_out;

    attn_split_kernel<<<dim3(HEADS, BATCH, ZMAX), 256>>>(
        kcache, vcache, btab, clen, hidden, rmsw);

    // reduce: PDL so residual/ctx loads overlap attn's tail
    {
        cudaLaunchConfig_t cfg = {};
        cfg.gridDim  = dim3(HEADS, BATCH);
        cfg.blockDim = dim3(128);
        cudaLaunchAttribute at[1];
        at[0].id = cudaLaunchAttributeProgrammaticStreamSerialization;
        at[0].val.programmaticStreamSerializationAllowed = 1;
        cfg.attrs = at;
        cfg.numAttrs = 1;
        cfg.stream = 0;
        cudaLaunchKernelEx(&cfg, attn_reduce_kernel, hidden, clen, out);
    }
}